// round 5
// baseline (speedup 1.0000x reference)
#include <cuda_runtime.h>
#include <cstdint>

#define BB   48
#define CC   64
#define HWN  16384        // 128*128
#define KK   4
#define HID  16
#define TPX  256          // pixels per conv block

// ---------------- scratch (no allocations allowed) ----------------
__device__ float g_mean[BB * CC];
__device__ float g_wmix[BB * CC * CC];   // [b][o][i]

// ---------------- kernel 1: per-(b,c) spatial mean ----------------
// 2 rows per block, 256 threads: 128 threads per row, warp-shuffle reduce.
__global__ void mean_kernel(const float* __restrict__ x) {
    int row  = blockIdx.x * 2 + (threadIdx.x >> 7);   // b*CC + c
    int lane = threadIdx.x & 127;
    const float4* p = (const float4*)(x + (size_t)row * HWN);
    float s = 0.f;
    #pragma unroll 4
    for (int i = lane; i < HWN / 4; i += 128) {
        float4 v = p[i];
        s += (v.x + v.y) + (v.z + v.w);
    }
    #pragma unroll
    for (int off = 16; off > 0; off >>= 1)
        s += __shfl_down_sync(0xffffffffu, s, off);
    __shared__ float red[8];
    if ((threadIdx.x & 31) == 0) red[threadIdx.x >> 5] = s;
    __syncthreads();
    if ((threadIdx.x & 127) == 0) {
        int w0 = (threadIdx.x >> 5);       // 0 or 4
        float t = red[w0] + red[w0 + 1] + red[w0 + 2] + red[w0 + 3];
        g_mean[row] = t * (1.0f / HWN);
    }
}

// ---------------- kernel 2: gate MLP + softmax + Wmix ----------------
__global__ void gate_kernel(const float* __restrict__ experts,
                            const float* __restrict__ fc1,
                            const float* __restrict__ fc2) {
    int b = blockIdx.x;
    int t = threadIdx.x;
    __shared__ float h[HID];
    __shared__ float alpha[KK];

    if (t < HID) {
        float s = 0.f;
        const float* gm = g_mean + b * CC;
        const float* w  = fc1 + t * CC;
        #pragma unroll 8
        for (int c = 0; c < CC; c++) s += gm[c] * w[c];
        h[t] = fmaxf(s, 0.f);
    }
    __syncthreads();
    if (t < KK) {
        float s = 0.f;
        #pragma unroll
        for (int j = 0; j < HID; j++) s += h[j] * fc2[t * HID + j];
        alpha[t] = s;                        // logits for now
    }
    __syncthreads();
    if (t == 0) {
        float m = alpha[0];
        #pragma unroll
        for (int k = 1; k < KK; k++) m = fmaxf(m, alpha[k]);
        float e[KK], sum = 0.f;
        #pragma unroll
        for (int k = 0; k < KK; k++) { e[k] = expf(alpha[k] - m); sum += e[k]; }
        float inv = 1.0f / sum;
        #pragma unroll
        for (int k = 0; k < KK; k++) alpha[k] = e[k] * inv;
    }
    __syncthreads();

    float a0 = alpha[0], a1 = alpha[1], a2 = alpha[2], a3 = alpha[3];
    float* wm = g_wmix + b * CC * CC;
    for (int idx = t; idx < CC * CC; idx += 256) {
        float w = a0 * experts[idx]
                + a1 * experts[CC * CC + idx]
                + a2 * experts[2 * CC * CC + idx]
                + a3 * experts[3 * CC * CC + idx];
        wm[idx] = w;
    }
}

// ---------------- kernel 3: y[b] = Wmix[b] @ x[b]  (packed f32x2) ----------------
// block: 256 threads = 8 warps, one batch b, one 256-pixel tile.
// Warp w owns output rows [w*8, w*8+8) = 4 f32x2 pairs (w-LDS = pure broadcast).
// Lane owns 8 pixels in TWO stride-4 chunks: {lane*4..+3} and {128+lane*4..+3}
//   -> each LDS.128 has 16B lane stride -> conflict-free (full 32-bank coverage).
// smem: xs[64][256] fp32 (64KB) + wsT[i][o] (16KB) = 80KB dynamic, 2 blocks/SM.
__global__ void __launch_bounds__(256, 2)
conv_kernel(const float* __restrict__ x, float* __restrict__ y) {
    extern __shared__ float smem[];
    float* xs = smem;               // [CC][TPX]
    float* ws = smem + CC * TPX;    // wsT: [i][o], row stride CC

    int b  = blockIdx.y;
    int p0 = blockIdx.x * TPX;
    int tid = threadIdx.x;

    const float* xb = x + (size_t)b * CC * HWN;

    // stage x tile (coalesced float4)
    for (int idx = tid; idx < CC * TPX / 4; idx += 256) {
        int row = idx >> 6;           // / (TPX/4)
        int c4  = idx & 63;
        float4 v = *(const float4*)(xb + (size_t)row * HWN + p0 + c4 * 4);
        *(float4*)(xs + row * TPX + c4 * 4) = v;
    }
    // stage Wmix transposed: wsT[i*CC + o] = wmix[o*CC + i]
    const float* wm = g_wmix + b * CC * CC;
    for (int idx = tid; idx < CC * CC; idx += 256) {
        int o = idx >> 6, i = idx & 63;
        ws[i * CC + o] = wm[idx];
    }
    __syncthreads();

    int wid  = tid >> 5;             // warp id: 8 output rows each
    int lane = tid & 31;
    int obase  = wid * 8;            // uniform within warp
    int pbase0 = lane * 4;           // chunk 0: pixels [lane*4, lane*4+4)
    int pbase1 = 128 + lane * 4;     // chunk 1: pixels [128+lane*4, ...)

    unsigned long long acc[4][8];    // [output pair][pixel: 0-3 chunk0, 4-7 chunk1]
    #pragma unroll
    for (int a = 0; a < 4; a++)
        #pragma unroll
        for (int p = 0; p < 8; p++) acc[a][p] = 0ull;   // (0.f,0.f)

    #pragma unroll 2
    for (int i = 0; i < CC; i++) {
        // 8 pixels (two conflict-free stride-4 float4 loads),
        // broadcast each into both f32x2 lanes
        float4 xv0 = *(const float4*)(xs + i * TPX + pbase0);
        float4 xv1 = *(const float4*)(xs + i * TPX + pbase1);
        unsigned long long x2[8];
        asm("mov.b64 %0, {%1,%1};" : "=l"(x2[0]) : "f"(xv0.x));
        asm("mov.b64 %0, {%1,%1};" : "=l"(x2[1]) : "f"(xv0.y));
        asm("mov.b64 %0, {%1,%1};" : "=l"(x2[2]) : "f"(xv0.z));
        asm("mov.b64 %0, {%1,%1};" : "=l"(x2[3]) : "f"(xv0.w));
        asm("mov.b64 %0, {%1,%1};" : "=l"(x2[4]) : "f"(xv1.x));
        asm("mov.b64 %0, {%1,%1};" : "=l"(x2[5]) : "f"(xv1.y));
        asm("mov.b64 %0, {%1,%1};" : "=l"(x2[6]) : "f"(xv1.z));
        asm("mov.b64 %0, {%1,%1};" : "=l"(x2[7]) : "f"(xv1.w));

        // 4 output-pairs of weights, warp-uniform address -> broadcast LDS
        const ulonglong2* wq = (const ulonglong2*)(ws + i * CC + obase);
        ulonglong2 q0 = wq[0], q1 = wq[1];
        unsigned long long w2[4] = { q0.x, q0.y, q1.x, q1.y };

        #pragma unroll
        for (int a = 0; a < 4; a++)
            #pragma unroll
            for (int p = 0; p < 8; p++)
                asm("fma.rn.f32x2 %0, %1, %2, %0;"
                    : "+l"(acc[a][p]) : "l"(w2[a]), "l"(x2[p]));
    }

    // epilogue: unpack pairs, store one float4 per chunk per output row
    float* yb = y + (size_t)b * CC * HWN + p0;
    #pragma unroll
    for (int a = 0; a < 4; a++) {
        float lo[8], hi[8];
        #pragma unroll
        for (int p = 0; p < 8; p++)
            asm("mov.b64 {%0,%1}, %2;" : "=f"(lo[p]), "=f"(hi[p]) : "l"(acc[a][p]));
        int oeven = obase + 2 * a;
        float* r0 = yb + (size_t)oeven * HWN;
        float* r1 = yb + (size_t)(oeven + 1) * HWN;
        *(float4*)(r0 + pbase0) = make_float4(lo[0], lo[1], lo[2], lo[3]);
        *(float4*)(r0 + pbase1) = make_float4(lo[4], lo[5], lo[6], lo[7]);
        *(float4*)(r1 + pbase0) = make_float4(hi[0], hi[1], hi[2], hi[3]);
        *(float4*)(r1 + pbase1) = make_float4(hi[4], hi[5], hi[6], hi[7]);
    }
}

// ---------------- launch ----------------
extern "C" void kernel_launch(void* const* d_in, const int* in_sizes, int n_in,
                              void* d_out, int out_size) {
    const float* x       = (const float*)d_in[0];
    const float* experts = (const float*)d_in[1];
    const float* fc1     = (const float*)d_in[2];
    const float* fc2     = (const float*)d_in[3];
    float* y = (float*)d_out;

    mean_kernel<<<BB * CC / 2, 256>>>(x);
    gate_kernel<<<BB, 256>>>(experts, fc1, fc2);

    const int smem_bytes = (CC * TPX + CC * CC) * sizeof(float);  // 80 KB
    cudaFuncSetAttribute(conv_kernel,
                         cudaFuncAttributeMaxDynamicSharedMemorySize, smem_bytes);
    dim3 grid(HWN / TPX, BB);
    conv_kernel<<<grid, 256, smem_bytes>>>(x, y);
}

// round 8
// speedup vs baseline: 1.8872x; 1.8872x over previous
#include <cuda_runtime.h>
#include <cuda_bf16.h>
#include <cstdint>

#define BB   48
#define CC   64
#define HWN  16384        // 128*128
#define KK   4
#define HID  16

#define TILE_P   128      // pixels per MMA tile
#define TILES_PB 4        // tiles per block
#define PPB      (TILE_P * TILES_PB)   // 512 pixels per block

// smem layout (bytes): swizzled bf16 tiles, 128-B rows
#define OFF_AHI  0          // [128 p][64 ch] bf16 = 16384
#define OFF_ALO  16384
#define OFF_BHI  32768      // [64 o][64 ch] bf16 = 8192
#define OFF_BLO  40960
#define SMEM_BYTES 49152

// ---------------- scratch ----------------
__device__ float g_mean[BB * CC];
__device__ float g_wmix[BB * CC * CC];   // [b][o][i]

// ---------------- helpers ----------------
__device__ __forceinline__ uint32_t smem_u32(const void* p) {
    uint32_t a;
    asm("{ .reg .u64 t; cvta.to.shared.u64 t, %1; cvt.u32.u64 %0, t; }"
        : "=r"(a) : "l"(p));
    return a;
}

__device__ __forceinline__ void split2(float a, float b, uint32_t& hi, uint32_t& lo) {
    __nv_bfloat16 ha = __float2bfloat16(a), hb = __float2bfloat16(b);
    float ra = a - __bfloat162float(ha);
    float rb = b - __bfloat162float(hb);
    __nv_bfloat16 la = __float2bfloat16(ra), lb = __float2bfloat16(rb);
    hi = (uint32_t)__bfloat16_as_ushort(ha) | ((uint32_t)__bfloat16_as_ushort(hb) << 16);
    lo = (uint32_t)__bfloat16_as_ushort(la) | ((uint32_t)__bfloat16_as_ushort(lb) << 16);
}

#define LDSM4(r0, r1, r2, r3, addr) \
    asm volatile("ldmatrix.sync.aligned.m8n8.x4.shared.b16 {%0,%1,%2,%3}, [%4];" \
        : "=r"(r0), "=r"(r1), "=r"(r2), "=r"(r3) : "r"(addr))

#define MMA16816(d, a0, a1, a2, a3, b0, b1) \
    asm volatile("mma.sync.aligned.m16n8k16.row.col.f32.bf16.bf16.f32 " \
        "{%0,%1,%2,%3}, {%4,%5,%6,%7}, {%8,%9}, {%0,%1,%2,%3};" \
        : "+f"((d)[0]), "+f"((d)[1]), "+f"((d)[2]), "+f"((d)[3]) \
        : "r"(a0), "r"(a1), "r"(a2), "r"(a3), "r"(b0), "r"(b1))

// ---------------- kernel 1: per-(b,c) spatial mean ----------------
__global__ void mean_kernel(const float* __restrict__ x) {
    int row  = blockIdx.x * 2 + (threadIdx.x >> 7);   // b*CC + c
    int lane = threadIdx.x & 127;
    const float4* p = (const float4*)(x + (size_t)row * HWN);
    float s = 0.f;
    #pragma unroll 4
    for (int i = lane; i < HWN / 4; i += 128) {
        float4 v = p[i];
        s += (v.x + v.y) + (v.z + v.w);
    }
    #pragma unroll
    for (int off = 16; off > 0; off >>= 1)
        s += __shfl_down_sync(0xffffffffu, s, off);
    __shared__ float red[8];
    if ((threadIdx.x & 31) == 0) red[threadIdx.x >> 5] = s;
    __syncthreads();
    if ((threadIdx.x & 127) == 0) {
        int w0 = (threadIdx.x >> 5);
        float t = red[w0] + red[w0 + 1] + red[w0 + 2] + red[w0 + 3];
        g_mean[row] = t * (1.0f / HWN);
    }
}

// ---------------- kernel 2: gate MLP + softmax + Wmix ----------------
__global__ void gate_kernel(const float* __restrict__ experts,
                            const float* __restrict__ fc1,
                            const float* __restrict__ fc2) {
    int b = blockIdx.x;
    int t = threadIdx.x;
    __shared__ float h[HID];
    __shared__ float alpha[KK];

    if (t < HID) {
        float s = 0.f;
        const float* gm = g_mean + b * CC;
        const float* w  = fc1 + t * CC;
        #pragma unroll 8
        for (int c = 0; c < CC; c++) s += gm[c] * w[c];
        h[t] = fmaxf(s, 0.f);
    }
    __syncthreads();
    if (t < KK) {
        float s = 0.f;
        #pragma unroll
        for (int j = 0; j < HID; j++) s += h[j] * fc2[t * HID + j];
        alpha[t] = s;
    }
    __syncthreads();
    if (t == 0) {
        float m = alpha[0];
        #pragma unroll
        for (int k = 1; k < KK; k++) m = fmaxf(m, alpha[k]);
        float e[KK], sum = 0.f;
        #pragma unroll
        for (int k = 0; k < KK; k++) { e[k] = expf(alpha[k] - m); sum += e[k]; }
        float inv = 1.0f / sum;
        #pragma unroll
        for (int k = 0; k < KK; k++) alpha[k] = e[k] * inv;
    }
    __syncthreads();

    float a0 = alpha[0], a1 = alpha[1], a2 = alpha[2], a3 = alpha[3];
    float* wm = g_wmix + b * CC * CC;
    for (int idx = t; idx < CC * CC; idx += 256) {
        float w = a0 * experts[idx]
                + a1 * experts[CC * CC + idx]
                + a2 * experts[2 * CC * CC + idx]
                + a3 * experts[3 * CC * CC + idx];
        wm[idx] = w;
    }
}

// ---------------- kernel 3: mma.sync bf16x3 conv ----------------
// D[p=128, o=64] = A[p][ch] @ W[o][ch]^T, 3-term bf16 split.
// smem rows = 128 B (64 bf16), 16B-column XOR swizzle: col' = col ^ (row & 7).
// All ldmatrix reads and STS.128 staging are conflict-free under this swizzle.
__global__ void __launch_bounds__(256)
conv_kernel(const float* __restrict__ x, float* __restrict__ y) {
    extern __shared__ char smem[];
    uint32_t sb = smem_u32(smem);

    int tid  = threadIdx.x;
    int wid  = tid >> 5;
    int lane = tid & 31;
    int b    = blockIdx.y;
    int P0   = blockIdx.x * PPB;

    // --- stage B (Wmix hi/lo), once per block: 512 chunks of 8 ch ---
    {
        const float* wm = g_wmix + b * CC * CC;
        #pragma unroll
        for (int r = 0; r < 2; r++) {
            int c    = tid + r * 256;       // chunk id
            int o    = c >> 3;
            int cblk = c & 7;
            const float* src = wm + o * CC + cblk * 8;
            uint32_t h0, l0, h1, l1, h2, l2, h3, l3;
            split2(src[0], src[1], h0, l0);
            split2(src[2], src[3], h1, l1);
            split2(src[4], src[5], h2, l2);
            split2(src[6], src[7], h3, l3);
            uint32_t off = o * 128 + ((cblk ^ (o & 7)) << 4);
            *(uint4*)(smem + OFF_BHI + off) = make_uint4(h0, h1, h2, h3);
            *(uint4*)(smem + OFF_BLO + off) = make_uint4(l0, l1, l2, l3);
        }
    }

    // staging role for A: thread -> pixel (t&127), ch half (t>>7)
    int sp   = tid & 127;
    int chb0 = (tid >> 7) * 4;          // first of 4 ch-blocks (8 ch each)

    // mma role: warp covers pixel rows [wid*16, wid*16+16)
    int pr0 = wid * 16;
    // A ldmatrix lane address pieces
    int arow = pr0 + (lane & 15);
    int asel = lane >> 4;               // 0: ch-lo 8, 1: ch-hi 8 of k-step
    // B ldmatrix lane address pieces (per n-pair q)
    int bor  = (lane & 7) + ((lane >> 4) & 1) * 8;   // o row offset within 16
    int bsel = (lane >> 3) & 1;

    // epilogue role
    int eprow = pr0 + (lane >> 2);
    int epcol = (lane & 3) * 2;

    for (int t = 0; t < TILES_PB; t++) {
        int pix = P0 + t * TILE_P;

        // --- stage A tile: 32 ch x 1 pixel per thread, split hi/lo ---
        {
            const float* xp = x + (size_t)b * CC * HWN + pix + sp;
            #pragma unroll
            for (int g = 0; g < 4; g++) {
                int cblk = chb0 + g;
                const float* src = xp + (size_t)(cblk * 8) * HWN;
                float v[8];
                #pragma unroll
                for (int j = 0; j < 8; j++) v[j] = src[(size_t)j * HWN];
                uint32_t h0, l0, h1, l1, h2, l2, h3, l3;
                split2(v[0], v[1], h0, l0);
                split2(v[2], v[3], h1, l1);
                split2(v[4], v[5], h2, l2);
                split2(v[6], v[7], h3, l3);
                uint32_t off = sp * 128 + ((cblk ^ (sp & 7)) << 4);
                *(uint4*)(smem + OFF_AHI + off) = make_uint4(h0, h1, h2, h3);
                *(uint4*)(smem + OFF_ALO + off) = make_uint4(l0, l1, l2, l3);
            }
        }
        __syncthreads();

        // --- MMA: 4 k-steps x (Ah*Bh + Ah*Bl + Al*Bh) over 8 n-tiles ---
        float acc[8][4];
        #pragma unroll
        for (int nt = 0; nt < 8; nt++)
            #pragma unroll
            for (int r = 0; r < 4; r++) acc[nt][r] = 0.f;

        #pragma unroll
        for (int ks = 0; ks < 4; ks++) {
            uint32_t aoff = arow * 128 + (((2 * ks + asel) ^ (arow & 7)) << 4);
            uint32_t ah0, ah1, ah2, ah3, al0, al1, al2, al3;
            LDSM4(ah0, ah1, ah2, ah3, sb + OFF_AHI + aoff);
            LDSM4(al0, al1, al2, al3, sb + OFF_ALO + aoff);

            uint32_t bh[8][2], bl[8][2];
            #pragma unroll
            for (int q = 0; q < 4; q++) {
                int orow = q * 16 + bor;
                uint32_t boff = orow * 128 + (((2 * ks + bsel) ^ (orow & 7)) << 4);
                LDSM4(bh[2*q][0], bh[2*q][1], bh[2*q+1][0], bh[2*q+1][1],
                      sb + OFF_BHI + boff);
                LDSM4(bl[2*q][0], bl[2*q][1], bl[2*q+1][0], bl[2*q+1][1],
                      sb + OFF_BLO + boff);
            }

            #pragma unroll
            for (int nt = 0; nt < 8; nt++)
                MMA16816(acc[nt], ah0, ah1, ah2, ah3, bh[nt][0], bh[nt][1]);
            #pragma unroll
            for (int nt = 0; nt < 8; nt++)
                MMA16816(acc[nt], ah0, ah1, ah2, ah3, bl[nt][0], bl[nt][1]);
            #pragma unroll
            for (int nt = 0; nt < 8; nt++)
                MMA16816(acc[nt], al0, al1, al2, al3, bh[nt][0], bh[nt][1]);
        }

        // --- epilogue: direct STG (4 x 32B segments per instruction) ---
        {
            float* yb = y + (size_t)b * CC * HWN + pix + eprow;
            #pragma unroll
            for (int nt = 0; nt < 8; nt++) {
                float* c0 = yb + (size_t)(nt * 8 + epcol) * HWN;
                float* c1 = c0 + HWN;
                c0[0] = acc[nt][0];
                c1[0] = acc[nt][1];
                c0[8] = acc[nt][2];
                c1[8] = acc[nt][3];
            }
        }
        __syncthreads();   // ldmatrix done before next tile's staging overwrites
    }
}

// ---------------- launch ----------------
extern "C" void kernel_launch(void* const* d_in, const int* in_sizes, int n_in,
                              void* d_out, int out_size) {
    const float* x       = (const float*)d_in[0];
    const float* experts = (const float*)d_in[1];
    const float* fc1     = (const float*)d_in[2];
    const float* fc2     = (const float*)d_in[3];
    float* y = (float*)d_out;

    mean_kernel<<<BB * CC / 2, 256>>>(x);
    gate_kernel<<<BB, 256>>>(experts, fc1, fc2);

    cudaFuncSetAttribute(conv_kernel,
                         cudaFuncAttributeMaxDynamicSharedMemorySize, SMEM_BYTES);
    dim3 grid(HWN / PPB, BB);          // (32, 48)
    conv_kernel<<<grid, 256, SMEM_BYTES>>>(x, y);
}